// round 2
// baseline (speedup 1.0000x reference)
#include <cuda_runtime.h>
#include <cstdint>
#include <math.h>

#define ENC_D 512
#define ATT_D 512
#define NB    32
#define NS    4096

// scratch for c[b,a] = dec_h@W_dec + b_dec + b_enc  (no device allocs allowed)
__device__ float g_c[NB * ATT_D];

__device__ __forceinline__ float f2tf32(float f) {
    unsigned u;
    asm("cvt.rna.tf32.f32 %0, %1;" : "=r"(u) : "f"(f));
    return __uint_as_float(u);
}

// ---------------------------------------------------------------------------
// Kernel 0: c[b,a] = sum_e dec_h[b,e] * W_dec[e,a] + b_dec[a] + b_enc[a]
// grid=32, block=512
// ---------------------------------------------------------------------------
__global__ void dec_proj_kernel(const float* __restrict__ dec_h,
                                const float* __restrict__ W_dec,
                                const float* __restrict__ b_dec,
                                const float* __restrict__ b_enc) {
    __shared__ float dh[ENC_D];
    int b = blockIdx.x;
    int a = threadIdx.x;
    dh[a] = dec_h[b * ENC_D + a];
    __syncthreads();
    float acc = 0.f;
#pragma unroll 8
    for (int e = 0; e < ENC_D; e++)
        acc += dh[e] * W_dec[e * ATT_D + a];
    g_c[b * ATT_D + a] = acc + b_dec[a] + b_enc[a];
}

// ---------------------------------------------------------------------------
// Kernel 1: att[b,s] = sum_a relu((input @ W_enc)[b,s,a] + c[b,a]) * w_att[a]
// tf32 mma.sync GEMM, BM=128 rows x BN=256 cols per pass, BK=16.
// 512 threads = 16 warps in a 4(M) x 4(N) grid; warp tile 32x64.
// grid = (32*4096)/128 = 1024 CTAs
// ---------------------------------------------------------------------------
#define BM 128
#define BN 256
#define BK 16
#define SPAD 8

__global__ __launch_bounds__(512, 1)
void score_kernel(const float* __restrict__ input,
                  const float* __restrict__ W_enc,
                  const float* __restrict__ w_att,
                  float* __restrict__ att) {
    __shared__ float As[BK][BM + SPAD];   // transposed: As[k][m], stride 136 (==8 mod 32)
    __shared__ float Bs[BK][BN + SPAD];   // Bs[k][n],  stride 264 (==8 mod 32)
    __shared__ float cs[BN];
    __shared__ float ws[BN];
    __shared__ float score[BM];

    const int tid  = threadIdx.x;
    const int lane = tid & 31;
    const int wid  = tid >> 5;
    const int wm   = wid & 3;          // 4 warps over M
    const int wn   = wid >> 2;         // 4 warps over N
    const int mbase = wm * 32;
    const int nbase = wn * 64;

    const int row0  = blockIdx.x * BM;
    const int batch = row0 / NS;       // BM divides NS -> whole CTA same batch

    if (tid < BM) score[tid] = 0.f;

    // A (input) global-load mapping: 4 threads per row, float4 each -> 128x16
    const int arow = tid >> 2;
    const int akq  = tid & 3;
    const float* Abase = input + (size_t)row0 * ENC_D;

    // B (W_enc) global-load mapping: 2x float4 per thread -> 16x256
    const int br0 = tid >> 6;          // rows 0..7 (and +8 for second load)
    const int bc4 = tid & 63;

    for (int ch = 0; ch < ATT_D / BN; ++ch) {
        __syncthreads();   // protect cs/ws rewrite vs previous epilogue readers
        if (tid < BN) {
            cs[tid] = g_c[batch * ATT_D + ch * BN + tid];
            ws[tid] = w_att[ch * BN + tid];
        }

        float acc[2][8][4];
#pragma unroll
        for (int mt = 0; mt < 2; mt++)
#pragma unroll
            for (int nt = 0; nt < 8; nt++)
#pragma unroll
                for (int i = 0; i < 4; i++) acc[mt][nt][i] = 0.f;

        // prefetch tile 0
        float4 aP  = *(const float4*)(Abase + (size_t)arow * ENC_D + akq * 4);
        float4 bP0 = *(const float4*)(W_enc + (size_t)br0 * ATT_D + ch * BN + bc4 * 4);
        float4 bP1 = *(const float4*)(W_enc + (size_t)(br0 + 8) * ATT_D + ch * BN + bc4 * 4);

        const int NT = ENC_D / BK;   // 32
        for (int t = 0; t < NT; ++t) {
            // stage current tile into smem (convert to tf32 once here)
            As[akq * 4 + 0][arow] = f2tf32(aP.x);
            As[akq * 4 + 1][arow] = f2tf32(aP.y);
            As[akq * 4 + 2][arow] = f2tf32(aP.z);
            As[akq * 4 + 3][arow] = f2tf32(aP.w);
            {
                float4 t0, t1;
                t0.x = f2tf32(bP0.x); t0.y = f2tf32(bP0.y);
                t0.z = f2tf32(bP0.z); t0.w = f2tf32(bP0.w);
                t1.x = f2tf32(bP1.x); t1.y = f2tf32(bP1.y);
                t1.z = f2tf32(bP1.z); t1.w = f2tf32(bP1.w);
                *(float4*)&Bs[br0][bc4 * 4]     = t0;
                *(float4*)&Bs[br0 + 8][bc4 * 4] = t1;
            }
            __syncthreads();

            // prefetch next tile (global loads fly under the mma work)
            if (t + 1 < NT) {
                aP  = *(const float4*)(Abase + (size_t)arow * ENC_D + (t + 1) * BK + akq * 4);
                bP0 = *(const float4*)(W_enc + (size_t)((t + 1) * BK + br0) * ATT_D + ch * BN + bc4 * 4);
                bP1 = *(const float4*)(W_enc + (size_t)((t + 1) * BK + br0 + 8) * ATT_D + ch * BN + bc4 * 4);
            }

#pragma unroll
            for (int ks = 0; ks < 2; ++ks) {
                const int k0 = ks * 8 + (lane & 3);
                // PTX m16n8k8.tf32 A fragment:
                //   reg0=(grp, tg) reg1=(grp+8, tg) reg2=(grp, tg+4) reg3=(grp+8, tg+4)
                float aR0[2], aR1[2], aR2[2], aR3[2];
#pragma unroll
                for (int mt = 0; mt < 2; ++mt) {
                    int m = mbase + mt * 16 + (lane >> 2);
                    aR0[mt] = As[k0][m];          // (grp,   tg)
                    aR1[mt] = As[k0][m + 8];      // (grp+8, tg)
                    aR2[mt] = As[k0 + 4][m];      // (grp,   tg+4)
                    aR3[mt] = As[k0 + 4][m + 8];  // (grp+8, tg+4)
                }
#pragma unroll
                for (int nt = 0; nt < 8; ++nt) {
                    int c = nbase + nt * 8 + (lane >> 2);
                    float b0 = Bs[k0][c];
                    float b1 = Bs[k0 + 4][c];
#pragma unroll
                    for (int mt = 0; mt < 2; ++mt) {
                        asm volatile(
                            "mma.sync.aligned.m16n8k8.row.col.f32.tf32.tf32.f32 "
                            "{%0,%1,%2,%3}, {%4,%5,%6,%7}, {%8,%9}, {%0,%1,%2,%3};"
                            : "+f"(acc[mt][nt][0]), "+f"(acc[mt][nt][1]),
                              "+f"(acc[mt][nt][2]), "+f"(acc[mt][nt][3])
                            : "r"(__float_as_uint(aR0[mt])), "r"(__float_as_uint(aR1[mt])),
                              "r"(__float_as_uint(aR2[mt])), "r"(__float_as_uint(aR3[mt])),
                              "r"(__float_as_uint(b0)), "r"(__float_as_uint(b1)));
                    }
                }
            }
            __syncthreads();
        }

        // epilogue: relu + dot with w_att, reduce into shared score[]
        float ps[4] = {0.f, 0.f, 0.f, 0.f};
#pragma unroll
        for (int mt = 0; mt < 2; ++mt) {
#pragma unroll
            for (int nt = 0; nt < 8; ++nt) {
                int c0 = nbase + nt * 8 + 2 * (lane & 3);
                float w0 = ws[c0], w1 = ws[c0 + 1];
                float d0 = cs[c0], d1 = cs[c0 + 1];
                float v;
                v = acc[mt][nt][0] + d0; ps[mt * 2 + 0] += fmaxf(v, 0.f) * w0;
                v = acc[mt][nt][1] + d1; ps[mt * 2 + 0] += fmaxf(v, 0.f) * w1;
                v = acc[mt][nt][2] + d0; ps[mt * 2 + 1] += fmaxf(v, 0.f) * w0;
                v = acc[mt][nt][3] + d1; ps[mt * 2 + 1] += fmaxf(v, 0.f) * w1;
            }
        }
        int r0 = mbase + (lane >> 2);
        atomicAdd(&score[r0],      ps[0]);
        atomicAdd(&score[r0 + 8],  ps[1]);
        atomicAdd(&score[r0 + 16], ps[2]);
        atomicAdd(&score[r0 + 24], ps[3]);
    }
    __syncthreads();
    if (tid < BM) att[row0 + tid] = score[tid];
}

// ---------------------------------------------------------------------------
// Kernel 2: in-place softmax over S per batch. grid=32, block=256.
// (b_att is a constant shift -> softmax-invariant -> dropped)
// ---------------------------------------------------------------------------
__global__ void softmax_kernel(float* __restrict__ att) {
    __shared__ float red[8];
    const int b = blockIdx.x;
    const int tid = threadIdx.x;
    const int lane = tid & 31;
    const int wid = tid >> 5;
    float* p = att + (size_t)b * NS;
    float4* p4 = (float4*)p;

    float v[16];
#pragma unroll
    for (int i = 0; i < 4; i++) {
        float4 x = p4[tid + i * 256];
        v[i * 4 + 0] = x.x; v[i * 4 + 1] = x.y;
        v[i * 4 + 2] = x.z; v[i * 4 + 3] = x.w;
    }
    float mx = -1e30f;
#pragma unroll
    for (int i = 0; i < 16; i++) mx = fmaxf(mx, v[i]);
#pragma unroll
    for (int off = 16; off > 0; off >>= 1)
        mx = fmaxf(mx, __shfl_xor_sync(0xFFFFFFFFu, mx, off));
    if (lane == 0) red[wid] = mx;
    __syncthreads();
    float gmx = red[0];
#pragma unroll
    for (int w = 1; w < 8; w++) gmx = fmaxf(gmx, red[w]);
    __syncthreads();

    float s = 0.f;
#pragma unroll
    for (int i = 0; i < 16; i++) { v[i] = expf(v[i] - gmx); s += v[i]; }
#pragma unroll
    for (int off = 16; off > 0; off >>= 1)
        s += __shfl_xor_sync(0xFFFFFFFFu, s, off);
    if (lane == 0) red[wid] = s;
    __syncthreads();
    float tot = 0.f;
#pragma unroll
    for (int w = 0; w < 8; w++) tot += red[w];
    float inv = 1.f / tot;

#pragma unroll
    for (int i = 0; i < 4; i++) {
        float4 y;
        y.x = v[i * 4 + 0] * inv; y.y = v[i * 4 + 1] * inv;
        y.z = v[i * 4 + 2] * inv; y.w = v[i * 4 + 3] * inv;
        p4[tid + i * 256] = y;
    }
}

// ---------------------------------------------------------------------------
// Kernel 3: weighted[b,e] += sum_s prob[b,s] * input[b,s,e]
// grid = 32 batches * 32 s-chunks, block=128 (each thread owns 4 e-columns)
// ---------------------------------------------------------------------------
__global__ void weighted_kernel(const float* __restrict__ input,
                                const float* __restrict__ prob,
                                float* __restrict__ wout) {
    __shared__ float ps[128];
    const int bx = blockIdx.x;
    const int b  = bx >> 5;
    const int sc = bx & 31;
    const int tid = threadIdx.x;

    ps[tid] = prob[(size_t)b * NS + sc * 128 + tid];
    __syncthreads();

    const float4* ip = (const float4*)(input + ((size_t)b * NS + (size_t)sc * 128) * ENC_D) + tid;
    float4 acc = make_float4(0.f, 0.f, 0.f, 0.f);
#pragma unroll 4
    for (int s = 0; s < 128; s++) {
        float4 x = ip[(size_t)s * 128];
        float pv = ps[s];
        acc.x += pv * x.x; acc.y += pv * x.y;
        acc.z += pv * x.z; acc.w += pv * x.w;
    }
    float* o = wout + b * ENC_D + tid * 4;
    atomicAdd(o + 0, acc.x);
    atomicAdd(o + 1, acc.y);
    atomicAdd(o + 2, acc.z);
    atomicAdd(o + 3, acc.w);
}

// ---------------------------------------------------------------------------
extern "C" void kernel_launch(void* const* d_in, const int* in_sizes, int n_in,
                              void* d_out, int out_size) {
    const float* input = (const float*)d_in[0];
    const float* dec_h = (const float*)d_in[1];
    const float* W_enc = (const float*)d_in[2];
    const float* b_enc = (const float*)d_in[3];
    const float* W_dec = (const float*)d_in[4];
    const float* b_dec = (const float*)d_in[5];
    const float* w_att = (const float*)d_in[6];
    // d_in[7] = b_att: constant logit shift, cancels in softmax.

    float* out      = (float*)d_out;
    float* weighted = out;                 // [32, 512]
    float* prob     = out + NB * ENC_D;    // [32, 4096] (also att scratch)

    cudaMemsetAsync(weighted, 0, NB * ENC_D * sizeof(float), 0);
    dec_proj_kernel<<<NB, ATT_D>>>(dec_h, W_dec, b_dec, b_enc);
    score_kernel<<<(NB * NS) / BM, 512>>>(input, W_enc, w_att, prob);
    softmax_kernel<<<NB, 256>>>(prob);
    weighted_kernel<<<NB * 32, 128>>>(input, prob, weighted);
}

// round 4
// speedup vs baseline: 1.2862x; 1.2862x over previous
#include <cuda_runtime.h>
#include <cstdint>
#include <math.h>

#define ENC_D 512
#define ATT_D 512
#define NB    32
#define NS    4096

// device scratch (no allocs allowed)
__device__ float g_c[NB * ATT_D];                       // dec projection
__device__ __align__(128) float g_Wt[ATT_D * ENC_D];    // W_enc^T [n][k], tf32-rounded

__device__ __forceinline__ float f2tf32(float f) {
    unsigned u;
    asm("cvt.rna.tf32.f32 %0, %1;" : "=r"(u) : "f"(f));
    return __uint_as_float(u);
}

__device__ __forceinline__ uint32_t smem_u32(const void* p) {
    uint32_t a;
    asm("{ .reg .u64 t; cvta.to.shared.u64 t, %1; cvt.u32.u64 %0, t; }" : "=r"(a) : "l"(p));
    return a;
}

__device__ __forceinline__ void cp16(uint32_t s, const void* g) {
    asm volatile("cp.async.cg.shared.global [%0], [%1], 16;" :: "r"(s), "l"(g));
}
#define CP_COMMIT() asm volatile("cp.async.commit_group;" ::: "memory")
#define CP_WAIT(n)  asm volatile("cp.async.wait_group %0;" :: "n"(n) : "memory")

// ---------------------------------------------------------------------------
// transpose + tf32-round W_enc [k][n] -> g_Wt [n][k]
// ---------------------------------------------------------------------------
__global__ void transpose_kernel(const float* __restrict__ W) {
    __shared__ float t[32][33];
    int k0 = blockIdx.x * 32, n0 = blockIdx.y * 32;
    int x = threadIdx.x, y = threadIdx.y;   // 32 x 8
#pragma unroll
    for (int i = 0; i < 32; i += 8)
        t[y + i][x] = W[(size_t)(k0 + y + i) * ATT_D + n0 + x];
    __syncthreads();
#pragma unroll
    for (int i = 0; i < 32; i += 8)
        g_Wt[(size_t)(n0 + y + i) * ENC_D + k0 + x] = f2tf32(t[x][y + i]);
}

// ---------------------------------------------------------------------------
// c[b,a] = dec_h @ W_dec + b_dec + b_enc
// ---------------------------------------------------------------------------
__global__ void dec_proj_kernel(const float* __restrict__ dec_h,
                                const float* __restrict__ W_dec,
                                const float* __restrict__ b_dec,
                                const float* __restrict__ b_enc) {
    __shared__ float dh[ENC_D];
    int b = blockIdx.x;
    int a = threadIdx.x;
    dh[a] = dec_h[b * ENC_D + a];
    __syncthreads();
    float acc = 0.f;
#pragma unroll 8
    for (int e = 0; e < ENC_D; e++)
        acc += dh[e] * W_dec[e * ATT_D + a];
    g_c[b * ATT_D + a] = acc + b_dec[a] + b_enc[a];
}

// ---------------------------------------------------------------------------
// score kernel: att[b,s] = sum_a relu((input@W_enc)[s,a] + c[b,a]) * w_att[a]
// tf32 mma.sync, BM=128 x BN=256 x BK=32, 3-stage cp.async pipeline,
// 512 threads (16 warps, 4M x 4N, warp tile 32x64), 2 N-chunks.
// ---------------------------------------------------------------------------
#define BM 128
#define BN 256
#define BK 32
#define NTILES 16                    // ENC_D / BK
#define STAGES 3
#define KSTR 36                      // row stride (floats): 32 + 4 pad
#define AS_BYTES (BM * KSTR * 4)     // 18432
#define BS_BYTES (BN * KSTR * 4)     // 36864
#define OFF_SCORE 0
#define OFF_CS    512
#define OFF_WS    1536
#define OFF_AS    3072
#define OFF_BS    (OFF_AS + STAGES * AS_BYTES)          // 58368
#define SMEM_TOTAL (OFF_BS + STAGES * BS_BYTES)         // 168960

__global__ __launch_bounds__(512, 1)
void score_kernel(const float* __restrict__ input,
                  const float* __restrict__ w_att,
                  float* __restrict__ att) {
    extern __shared__ char smem[];
    const uint32_t sbase = smem_u32(smem);
    float* smf   = (float*)smem;
    float* score = smf + (OFF_SCORE >> 2);
    float* cs    = smf + (OFF_CS >> 2);
    float* ws    = smf + (OFF_WS >> 2);

    const int tid  = threadIdx.x;
    const int lane = tid & 31;
    const int wid  = tid >> 5;
    const int mbase = (wid & 3) * 32;
    const int nbase = (wid >> 2) * 64;
    const int row0  = blockIdx.x * BM;
    const int batch = row0 / NS;

    // cp.async thread mapping: row = idx>>3, 16B col = idx&7
    const int arow = tid >> 3;       // +64 for second A chunk
    const int ac4  = tid & 7;

    if (tid < BM) score[tid] = 0.f;

    for (int ch = 0; ch < 2; ++ch) {
        __syncthreads();             // buffers + cs/ws free (prev chunk drained)
        if (tid < BN) {
            cs[tid] = g_c[batch * ATT_D + ch * BN + tid];
            ws[tid] = w_att[ch * BN + tid];
        }

        float acc[2][8][4];
#pragma unroll
        for (int mt = 0; mt < 2; mt++)
#pragma unroll
            for (int nt = 0; nt < 8; nt++)
#pragma unroll
                for (int i = 0; i < 4; i++) acc[mt][nt][i] = 0.f;

        // ---- prologue: issue tiles 0,1 ----
#pragma unroll
        for (int p = 0; p < STAGES - 1; ++p) {
            const int kk = p * BK;
            uint32_t as = sbase + OFF_AS + p * AS_BYTES;
            uint32_t bs = sbase + OFF_BS + p * BS_BYTES;
#pragma unroll
            for (int i = 0; i < 2; i++)
                cp16(as + (arow + i * 64) * (KSTR * 4) + ac4 * 16,
                     input + (size_t)(row0 + arow + i * 64) * ENC_D + kk + ac4 * 4);
#pragma unroll
            for (int i = 0; i < 4; i++)
                cp16(bs + (arow + i * 64) * (KSTR * 4) + ac4 * 16,
                     g_Wt + (size_t)(ch * BN + arow + i * 64) * ENC_D + kk + ac4 * 4);
            CP_COMMIT();
        }

        int st = 0;                  // stage of tile t
        for (int t = 0; t < NTILES; ++t) {
            if (t < NTILES - 1) CP_WAIT(1); else CP_WAIT(0);
            __syncthreads();

            // issue tile t+2
            if (t + STAGES - 1 < NTILES) {
                int sn = st + 2; if (sn >= STAGES) sn -= STAGES;
                const int kk = (t + 2) * BK;
                uint32_t as = sbase + OFF_AS + sn * AS_BYTES;
                uint32_t bs = sbase + OFF_BS + sn * BS_BYTES;
#pragma unroll
                for (int i = 0; i < 2; i++)
                    cp16(as + (arow + i * 64) * (KSTR * 4) + ac4 * 16,
                         input + (size_t)(row0 + arow + i * 64) * ENC_D + kk + ac4 * 4);
#pragma unroll
                for (int i = 0; i < 4; i++)
                    cp16(bs + (arow + i * 64) * (KSTR * 4) + ac4 * 16,
                         g_Wt + (size_t)(ch * BN + arow + i * 64) * ENC_D + kk + ac4 * 4);
                CP_COMMIT();
            }

            // compute tile t from stage st
            const float* As = smf + (OFF_AS >> 2) + st * (AS_BYTES >> 2);
            const float* Bs = smf + (OFF_BS >> 2) + st * (BS_BYTES >> 2);
#pragma unroll
            for (int ks = 0; ks < 4; ++ks) {
                const int k0 = ks * 8 + (lane & 3);
                // m16n8k8.tf32 A frag: r0=(g,tg) r1=(g+8,tg) r2=(g,tg+4) r3=(g+8,tg+4)
                float aR0[2], aR1[2], aR2[2], aR3[2];
#pragma unroll
                for (int mt = 0; mt < 2; ++mt) {
                    int m = mbase + mt * 16 + (lane >> 2);
                    aR0[mt] = As[m * KSTR + k0];
                    aR1[mt] = As[(m + 8) * KSTR + k0];
                    aR2[mt] = As[m * KSTR + k0 + 4];
                    aR3[mt] = As[(m + 8) * KSTR + k0 + 4];
                }
#pragma unroll
                for (int nt = 0; nt < 8; ++nt) {
                    int c = nbase + nt * 8 + (lane >> 2);
                    float b0 = Bs[c * KSTR + k0];
                    float b1 = Bs[c * KSTR + k0 + 4];
#pragma unroll
                    for (int mt = 0; mt < 2; ++mt) {
                        asm volatile(
                            "mma.sync.aligned.m16n8k8.row.col.f32.tf32.tf32.f32 "
                            "{%0,%1,%2,%3}, {%4,%5,%6,%7}, {%8,%9}, {%0,%1,%2,%3};"
                            : "+f"(acc[mt][nt][0]), "+f"(acc[mt][nt][1]),
                              "+f"(acc[mt][nt][2]), "+f"(acc[mt][nt][3])
                            : "r"(__float_as_uint(aR0[mt])), "r"(__float_as_uint(aR1[mt])),
                              "r"(__float_as_uint(aR2[mt])), "r"(__float_as_uint(aR3[mt])),
                              "r"(__float_as_uint(b0)), "r"(__float_as_uint(b1)));
                    }
                }
            }
            if (++st >= STAGES) st = 0;
        }

        // epilogue: relu + dot with w_att, reduce into shared score[]
        float ps[4] = {0.f, 0.f, 0.f, 0.f};
#pragma unroll
        for (int mt = 0; mt < 2; ++mt) {
#pragma unroll
            for (int nt = 0; nt < 8; ++nt) {
                int c0 = nbase + nt * 8 + 2 * (lane & 3);
                float w0 = ws[c0], w1 = ws[c0 + 1];
                float d0 = cs[c0], d1 = cs[c0 + 1];
                float v;
                v = acc[mt][nt][0] + d0; ps[mt * 2 + 0] += fmaxf(v, 0.f) * w0;
                v = acc[mt][nt][1] + d1; ps[mt * 2 + 0] += fmaxf(v, 0.f) * w1;
                v = acc[mt][nt][2] + d0; ps[mt * 2 + 1] += fmaxf(v, 0.f) * w0;
                v = acc[mt][nt][3] + d1; ps[mt * 2 + 1] += fmaxf(v, 0.f) * w1;
            }
        }
        int r0 = mbase + (lane >> 2);
        atomicAdd(&score[r0],      ps[0]);
        atomicAdd(&score[r0 + 8],  ps[1]);
        atomicAdd(&score[r0 + 16], ps[2]);
        atomicAdd(&score[r0 + 24], ps[3]);
    }
    __syncthreads();
    if (tid < BM) att[row0 + tid] = score[tid];
}

// ---------------------------------------------------------------------------
// softmax over S per batch (b_att cancels)
// ---------------------------------------------------------------------------
__global__ void softmax_kernel(float* __restrict__ att) {
    __shared__ float red[8];
    const int b = blockIdx.x;
    const int tid = threadIdx.x;
    const int lane = tid & 31;
    const int wid = tid >> 5;
    float4* p4 = (float4*)(att + (size_t)b * NS);

    float v[16];
#pragma unroll
    for (int i = 0; i < 4; i++) {
        float4 x = p4[tid + i * 256];
        v[i * 4 + 0] = x.x; v[i * 4 + 1] = x.y;
        v[i * 4 + 2] = x.z; v[i * 4 + 3] = x.w;
    }
    float mx = -1e30f;
#pragma unroll
    for (int i = 0; i < 16; i++) mx = fmaxf(mx, v[i]);
#pragma unroll
    for (int off = 16; off > 0; off >>= 1)
        mx = fmaxf(mx, __shfl_xor_sync(0xFFFFFFFFu, mx, off));
    if (lane == 0) red[wid] = mx;
    __syncthreads();
    float gmx = red[0];
#pragma unroll
    for (int w = 1; w < 8; w++) gmx = fmaxf(gmx, red[w]);
    __syncthreads();

    float s = 0.f;
#pragma unroll
    for (int i = 0; i < 16; i++) { v[i] = expf(v[i] - gmx); s += v[i]; }
#pragma unroll
    for (int off = 16; off > 0; off >>= 1)
        s += __shfl_xor_sync(0xFFFFFFFFu, s, off);
    if (lane == 0) red[wid] = s;
    __syncthreads();
    float tot = 0.f;
#pragma unroll
    for (int w = 0; w < 8; w++) tot += red[w];
    float inv = 1.f / tot;

#pragma unroll
    for (int i = 0; i < 4; i++) {
        float4 y;
        y.x = v[i * 4 + 0] * inv; y.y = v[i * 4 + 1] * inv;
        y.z = v[i * 4 + 2] * inv; y.w = v[i * 4 + 3] * inv;
        p4[tid + i * 256] = y;
    }
}

// ---------------------------------------------------------------------------
// weighted[b,e] += sum_s prob[b,s] * input[b,s,e]
// ---------------------------------------------------------------------------
__global__ void weighted_kernel(const float* __restrict__ input,
                                const float* __restrict__ prob,
                                float* __restrict__ wout) {
    __shared__ float ps[128];
    const int bx = blockIdx.x;
    const int b  = bx >> 5;
    const int sc = bx & 31;
    const int tid = threadIdx.x;

    ps[tid] = prob[(size_t)b * NS + sc * 128 + tid];
    __syncthreads();

    const float4* ip = (const float4*)(input + ((size_t)b * NS + (size_t)sc * 128) * ENC_D) + tid;
    float4 acc = make_float4(0.f, 0.f, 0.f, 0.f);
#pragma unroll 4
    for (int s = 0; s < 128; s++) {
        float4 x = ip[(size_t)s * 128];
        float pv = ps[s];
        acc.x += pv * x.x; acc.y += pv * x.y;
        acc.z += pv * x.z; acc.w += pv * x.w;
    }
    float* o = wout + b * ENC_D + tid * 4;
    atomicAdd(o + 0, acc.x);
    atomicAdd(o + 1, acc.y);
    atomicAdd(o + 2, acc.z);
    atomicAdd(o + 3, acc.w);
}

// ---------------------------------------------------------------------------
extern "C" void kernel_launch(void* const* d_in, const int* in_sizes, int n_in,
                              void* d_out, int out_size) {
    const float* input = (const float*)d_in[0];
    const float* dec_h = (const float*)d_in[1];
    const float* W_enc = (const float*)d_in[2];
    const float* b_enc = (const float*)d_in[3];
    const float* W_dec = (const float*)d_in[4];
    const float* b_dec = (const float*)d_in[5];
    const float* w_att = (const float*)d_in[6];
    // d_in[7] = b_att: constant logit shift, cancels in softmax.

    float* out      = (float*)d_out;
    float* weighted = out;                 // [32, 512]
    float* prob     = out + NB * ENC_D;    // [32, 4096] (also att scratch)

    cudaFuncSetAttribute(score_kernel,
                         cudaFuncAttributeMaxDynamicSharedMemorySize, SMEM_TOTAL);

    cudaMemsetAsync(weighted, 0, NB * ENC_D * sizeof(float), 0);
    transpose_kernel<<<dim3(16, 16), dim3(32, 8)>>>(W_enc);
    dec_proj_kernel<<<NB, ATT_D>>>(dec_h, W_dec, b_dec, b_enc);
    score_kernel<<<(NB * NS) / BM, 512, SMEM_TOTAL>>>(input, w_att, prob);
    softmax_kernel<<<NB, 256>>>(prob);
    weighted_kernel<<<NB * 32, 128>>>(input, prob, weighted);
}